// round 1
// baseline (speedup 1.0000x reference)
#include <cuda_runtime.h>
#include <cstdint>

#define N_NODES 100000
#define N_EDGES 1000000
#define D 64
#define IN_DIM 192
#define LATENT 32
#define OUT_DIM 64

// Scratch (static device globals — no runtime allocation)
__device__ float g_sums[(size_t)N_NODES * D];   // 25.6 MB
__device__ float g_cnt[N_NODES];

// ---------------------------------------------------------------------------
// Kernel 1: zero the scratch buffers
// ---------------------------------------------------------------------------
__global__ void zero_kernel() {
    const int total4 = (N_NODES * D) / 4;  // 1.6M float4
    float4 z = make_float4(0.f, 0.f, 0.f, 0.f);
    for (int i = blockIdx.x * blockDim.x + threadIdx.x; i < total4;
         i += gridDim.x * blockDim.x) {
        reinterpret_cast<float4*>(g_sums)[i] = z;
    }
    for (int i = blockIdx.x * blockDim.x + threadIdx.x; i < N_NODES;
         i += gridDim.x * blockDim.x) {
        g_cnt[i] = 0.f;
    }
}

// ---------------------------------------------------------------------------
// Kernel 2: edge scatter. 16 threads per edge, each does one float4 chunk.
// Vectorized fp32 L2 reduction (sm_90+): red.global.add.v4.f32
// ---------------------------------------------------------------------------
__global__ void scatter_kernel(const float* __restrict__ edge_attr,
                               const int* __restrict__ recv) {
    long long gid = (long long)blockIdx.x * blockDim.x + threadIdx.x;
    int e = (int)(gid >> 4);
    int c = (int)(gid & 15);
    if (e >= N_EDGES) return;

    int r = __ldg(&recv[e]);
    float4 v = reinterpret_cast<const float4*>(edge_attr)[(size_t)e * 16 + c];
    float4* dst = reinterpret_cast<float4*>(g_sums) + (size_t)r * 16 + c;
    asm volatile("red.global.add.v4.f32 [%0], {%1, %2, %3, %4};"
                 :: "l"(dst), "f"(v.x), "f"(v.y), "f"(v.z), "f"(v.w)
                 : "memory");
    if (c == 0) atomicAdd(&g_cnt[r], 1.0f);
}

// ---------------------------------------------------------------------------
// Kernel 3: fused mean + gather + concat + 2-layer MLP.
// One warp per node. Weights staged in shared once per block (grid-stride
// over nodes so the weight load is amortized across ~85 nodes per warp).
// ---------------------------------------------------------------------------
__global__ __launch_bounds__(256)
void mlp_kernel(const float* __restrict__ node_attr,
                const float* __restrict__ global_attr,
                const float* __restrict__ W1,
                const float* __restrict__ b1,
                const float* __restrict__ W2,
                const float* __restrict__ b2,
                const int* __restrict__ ng,
                float* __restrict__ out) {
    __shared__ float sW1[IN_DIM * LATENT];   // 6144 floats, [k][j] layout
    __shared__ float sW2[LATENT * OUT_DIM];  // 2048 floats, [j][o] layout
    __shared__ float sb1[LATENT];
    __shared__ float sb2[OUT_DIM];
    __shared__ __align__(16) float xbuf[8][IN_DIM];  // per-warp concat input

    const int tid = threadIdx.x;
    for (int i = tid; i < IN_DIM * LATENT; i += 256) sW1[i] = W1[i];
    for (int i = tid; i < LATENT * OUT_DIM; i += 256) sW2[i] = W2[i];
    if (tid < LATENT) sb1[tid] = b1[tid];
    if (tid >= 128 && tid < 128 + OUT_DIM) sb2[tid - 128] = b2[tid - 128];
    __syncthreads();

    const int warp = tid >> 5;
    const int lane = tid & 31;
    float* xw = xbuf[warp];

    for (int n = blockIdx.x * 8 + warp; n < N_NODES; n += gridDim.x * 8) {
        // ---- stage concat input: [node_attr | mean_recv_edges | global] ----
        float cntv = g_cnt[n];
        float inv = 1.0f / fmaxf(cntv, 1.0f);
        int g = __ldg(&ng[n]);

        float2 na = reinterpret_cast<const float2*>(node_attr)[(size_t)n * 32 + lane];
        float2 sm = reinterpret_cast<const float2*>(g_sums)[(size_t)n * 32 + lane];
        float2 ga = reinterpret_cast<const float2*>(global_attr)[(size_t)g * 32 + lane];

        xw[lane * 2 + 0]       = na.x;
        xw[lane * 2 + 1]       = na.y;
        xw[64 + lane * 2 + 0]  = sm.x * inv;
        xw[64 + lane * 2 + 1]  = sm.y * inv;
        xw[128 + lane * 2 + 0] = ga.x;
        xw[128 + lane * 2 + 1] = ga.y;
        __syncwarp();

        // ---- layer 1: h[lane] = relu(b1[lane] + x . W1[:,lane]) ----
        float h = sb1[lane];
        #pragma unroll
        for (int k = 0; k < IN_DIM; k += 4) {
            float4 xk = *reinterpret_cast<const float4*>(&xw[k]);
            h = fmaf(xk.x, sW1[(k + 0) * LATENT + lane], h);
            h = fmaf(xk.y, sW1[(k + 1) * LATENT + lane], h);
            h = fmaf(xk.z, sW1[(k + 2) * LATENT + lane], h);
            h = fmaf(xk.w, sW1[(k + 3) * LATENT + lane], h);
        }
        h = fmaxf(h, 0.0f);

        // ---- layer 2: out[o] = b2[o] + sum_j h_j * W2[j][o], o = lane, lane+32
        float o0 = sb2[lane];
        float o1 = sb2[lane + 32];
        #pragma unroll
        for (int j = 0; j < LATENT; j++) {
            float hj = __shfl_sync(0xffffffffu, h, j);
            o0 = fmaf(hj, sW2[j * OUT_DIM + lane], o0);
            o1 = fmaf(hj, sW2[j * OUT_DIM + lane + 32], o1);
        }

        out[(size_t)n * OUT_DIM + lane]      = o0;
        out[(size_t)n * OUT_DIM + lane + 32] = o1;
        __syncwarp();  // xbuf reuse guard for next iteration
    }
}

// ---------------------------------------------------------------------------
extern "C" void kernel_launch(void* const* d_in, const int* in_sizes, int n_in,
                              void* d_out, int out_size) {
    const float* node_attr   = (const float*)d_in[0];
    const float* edge_attr   = (const float*)d_in[1];
    const float* global_attr = (const float*)d_in[2];
    const float* W1          = (const float*)d_in[3];
    const float* b1          = (const float*)d_in[4];
    const float* W2          = (const float*)d_in[5];
    const float* b2          = (const float*)d_in[6];
    const int*   recv        = (const int*)d_in[7];
    const int*   ng          = (const int*)d_in[8];
    float* out = (float*)d_out;

    // 1) zero scratch
    zero_kernel<<<1184, 256>>>();

    // 2) edge scatter: 16M threads (16 per edge)
    {
        long long total = (long long)N_EDGES * 16;
        int threads = 256;
        int blocks = (int)((total + threads - 1) / threads);
        scatter_kernel<<<blocks, threads>>>(edge_attr, recv);
    }

    // 3) fused mean + MLP: warp-per-node, grid-stride
    mlp_kernel<<<1184, 256>>>(node_attr, global_attr, W1, b1, W2, b2, ng, out);
}

// round 2
// speedup vs baseline: 1.4505x; 1.4505x over previous
#include <cuda_runtime.h>
#include <cstdint>

#define N_NODES 100000
#define N_EDGES 1000000
#define D 64
#define LATENT 32
#define OUT_DIM 64
#define XS_STRIDE 66

// Scratch (static device globals — no runtime allocation)
__device__ float g_sums[(size_t)N_NODES * D];   // 25.6 MB
__device__ float g_cnt[N_NODES];
__device__ float g_G[64 * LATENT];              // global_attr @ W1[128:192] + b1

// ---------------------------------------------------------------------------
// f32x2 packed helpers (Blackwell FFMA2 — only reachable via PTX)
// ---------------------------------------------------------------------------
__device__ __forceinline__ uint64_t pack2(float a, float b) {
    uint64_t r; asm("mov.b64 %0, {%1, %2};" : "=l"(r) : "f"(a), "f"(b)); return r;
}
__device__ __forceinline__ void unpack2(uint64_t v, float& a, float& b) {
    asm("mov.b64 {%0, %1}, %2;" : "=f"(a), "=f"(b) : "l"(v));
}
__device__ __forceinline__ void ffma2(uint64_t& acc, uint64_t x, uint64_t w) {
    asm("fma.rn.f32x2 %0, %1, %2, %0;" : "+l"(acc) : "l"(x), "l"(w));
}

// ---------------------------------------------------------------------------
// Kernel 1: zero scratch + precompute G[b][j] = b1[j] + global[b] . W1[128+k][j]
// ---------------------------------------------------------------------------
__global__ __launch_bounds__(256)
void zero_kernel(const float* __restrict__ global_attr,
                 const float* __restrict__ W1,
                 const float* __restrict__ b1) {
    const int gtid = blockIdx.x * blockDim.x + threadIdx.x;
    const int total4 = (N_NODES * D) / 4;
    float4 z = make_float4(0.f, 0.f, 0.f, 0.f);
    for (int i = gtid; i < total4; i += gridDim.x * blockDim.x)
        reinterpret_cast<float4*>(g_sums)[i] = z;
    for (int i = gtid; i < N_NODES; i += gridDim.x * blockDim.x)
        g_cnt[i] = 0.f;

    if (blockIdx.x == 0) {
        const int lane = threadIdx.x & 31;
        const int p = threadIdx.x >> 5;   // 0..7 -> batch rows p*8..p*8+7
        float acc[8];
        #pragma unroll
        for (int i = 0; i < 8; i++) acc[i] = b1[lane];
        for (int k = 0; k < D; k++) {
            float w = W1[(2 * D + k) * LATENT + lane];
            #pragma unroll
            for (int i = 0; i < 8; i++)
                acc[i] = fmaf(global_attr[(p * 8 + i) * D + k], w, acc[i]);
        }
        #pragma unroll
        for (int i = 0; i < 8; i++) g_G[(p * 8 + i) * LATENT + lane] = acc[i];
    }
}

// ---------------------------------------------------------------------------
// Kernel 2: edge scatter. 16 threads per edge, vectorized L2 reduction.
// ---------------------------------------------------------------------------
__global__ void scatter_kernel(const float* __restrict__ edge_attr,
                               const int* __restrict__ recv) {
    long long gid = (long long)blockIdx.x * blockDim.x + threadIdx.x;
    int e = (int)(gid >> 4);
    int c = (int)(gid & 15);
    if (e >= N_EDGES) return;

    int r = __ldg(&recv[e]);
    float4 v = reinterpret_cast<const float4*>(edge_attr)[(size_t)e * 16 + c];
    float4* dst = reinterpret_cast<float4*>(g_sums) + (size_t)r * 16 + c;
    asm volatile("red.global.add.v4.f32 [%0], {%1, %2, %3, %4};"
                 :: "l"(dst), "f"(v.x), "f"(v.y), "f"(v.z), "f"(v.w)
                 : "memory");
    if (c == 0) atomicAdd(&g_cnt[r], 1.0f);
}

// ---------------------------------------------------------------------------
// Kernel 3: register-tiled fused mean + MLP with packed f32x2 FMA.
// Block = 64-node tile; lane = latent col; warp owns 8 nodes (4 f32x2 pairs).
// ---------------------------------------------------------------------------
__global__ __launch_bounds__(256)
void mlp_kernel(const float* __restrict__ node_attr,
                const float* __restrict__ W1,
                const float* __restrict__ W2,
                const float* __restrict__ b2,
                const int* __restrict__ ng,
                float* __restrict__ out) {
    __shared__ float sW1[2 * D * LATENT];          // 16 KB: rows 0..127 of W1
    __shared__ float sW2[LATENT * OUT_DIM];        // 8 KB
    __shared__ float sb2[OUT_DIM];
    __shared__ __align__(16) float xs[D * XS_STRIDE];  // 16.9 KB, reused for h

    const int tid = threadIdx.x;
    const int tile = blockIdx.x * 64;

    for (int i = tid; i < 2 * D * LATENT; i += 256) sW1[i] = W1[i];
    for (int i = tid; i < LATENT * OUT_DIM; i += 256) sW2[i] = W2[i];
    if (tid < OUT_DIM) sb2[tid] = b2[tid];

    const int lane = tid & 31;
    const int p = tid >> 5;           // warp id = node group
    const int nbase = tile + p * 8;

    // init accumulators from precomputed global projection G
    uint64_t h2[4];
    #pragma unroll
    for (int q = 0; q < 4; q++) {
        int n0 = nbase + 2 * q, n1 = n0 + 1;
        int g0 = (n0 < N_NODES) ? __ldg(&ng[n0]) : 0;
        int g1 = (n1 < N_NODES) ? __ldg(&ng[n1]) : 0;
        h2[q] = pack2(g_G[g0 * LATENT + lane], g_G[g1 * LATENT + lane]);
    }

    const int kq = tid & 15;          // float4 slot: k = kq*4 .. kq*4+3
    const int srow = tid >> 4;        // node sub-slot 0..15

    // ---- pass 1: stage node_attr (k-major), accumulate k = 0..63 ----
    #pragma unroll
    for (int it = 0; it < 4; it++) {
        int nn = it * 16 + srow;
        int n = tile + nn;
        float4 v = make_float4(0.f, 0.f, 0.f, 0.f);
        if (n < N_NODES)
            v = reinterpret_cast<const float4*>(node_attr)[(size_t)n * 16 + kq];
        int k0 = kq * 4;
        xs[(k0 + 0) * XS_STRIDE + nn] = v.x;
        xs[(k0 + 1) * XS_STRIDE + nn] = v.y;
        xs[(k0 + 2) * XS_STRIDE + nn] = v.z;
        xs[(k0 + 3) * XS_STRIDE + nn] = v.w;
    }
    __syncthreads();

    #pragma unroll 4
    for (int k = 0; k < D; k++) {
        float w = sW1[k * LATENT + lane];
        uint64_t w2 = pack2(w, w);
        const uint64_t* xr =
            reinterpret_cast<const uint64_t*>(&xs[k * XS_STRIDE + p * 8]);
        #pragma unroll
        for (int q = 0; q < 4; q++) ffma2(h2[q], xr[q], w2);
    }
    __syncthreads();

    // ---- pass 2: stage mean aggregated edges, accumulate k = 64..127 ----
    #pragma unroll
    for (int it = 0; it < 4; it++) {
        int nn = it * 16 + srow;
        int n = tile + nn;
        float4 v = make_float4(0.f, 0.f, 0.f, 0.f);
        if (n < N_NODES) {
            v = reinterpret_cast<const float4*>(g_sums)[(size_t)n * 16 + kq];
            float inv = 1.0f / fmaxf(g_cnt[n], 1.0f);
            v.x *= inv; v.y *= inv; v.z *= inv; v.w *= inv;
        }
        int k0 = kq * 4;
        xs[(k0 + 0) * XS_STRIDE + nn] = v.x;
        xs[(k0 + 1) * XS_STRIDE + nn] = v.y;
        xs[(k0 + 2) * XS_STRIDE + nn] = v.z;
        xs[(k0 + 3) * XS_STRIDE + nn] = v.w;
    }
    __syncthreads();

    #pragma unroll 4
    for (int k = 0; k < D; k++) {
        float w = sW1[(D + k) * LATENT + lane];
        uint64_t w2 = pack2(w, w);
        const uint64_t* xr =
            reinterpret_cast<const uint64_t*>(&xs[k * XS_STRIDE + p * 8]);
        #pragma unroll
        for (int q = 0; q < 4; q++) ffma2(h2[q], xr[q], w2);
    }
    __syncthreads();

    // ---- relu, park h in xs (j-major) ----
    #pragma unroll
    for (int q = 0; q < 4; q++) {
        float a, b;
        unpack2(h2[q], a, b);
        a = fmaxf(a, 0.f);
        b = fmaxf(b, 0.f);
        *reinterpret_cast<uint64_t*>(&xs[lane * XS_STRIDE + p * 8 + 2 * q]) =
            pack2(a, b);
    }
    __syncthreads();

    // ---- layer 2 ----
    uint64_t o2[4][2];
    #pragma unroll
    for (int q = 0; q < 4; q++) {
        o2[q][0] = pack2(sb2[lane], sb2[lane]);
        o2[q][1] = pack2(sb2[lane + 32], sb2[lane + 32]);
    }
    #pragma unroll 4
    for (int j = 0; j < LATENT; j++) {
        float wa = sW2[j * OUT_DIM + lane];
        float wb = sW2[j * OUT_DIM + lane + 32];
        uint64_t w0 = pack2(wa, wa);
        uint64_t w1 = pack2(wb, wb);
        const uint64_t* hr =
            reinterpret_cast<const uint64_t*>(&xs[j * XS_STRIDE + p * 8]);
        #pragma unroll
        for (int q = 0; q < 4; q++) {
            uint64_t x = hr[q];
            ffma2(o2[q][0], x, w0);
            ffma2(o2[q][1], x, w1);
        }
    }

    // ---- store ----
    #pragma unroll
    for (int q = 0; q < 4; q++) {
        int n0 = nbase + 2 * q;
        float a0, c0, a1, c1;
        unpack2(o2[q][0], a0, c0);  // a0 -> node n0, c0 -> node n0+1 (col lane)
        unpack2(o2[q][1], a1, c1);  // cols lane+32
        if (n0 < N_NODES) {
            out[(size_t)n0 * OUT_DIM + lane] = a0;
            out[(size_t)n0 * OUT_DIM + lane + 32] = a1;
        }
        if (n0 + 1 < N_NODES) {
            out[(size_t)(n0 + 1) * OUT_DIM + lane] = c0;
            out[(size_t)(n0 + 1) * OUT_DIM + lane + 32] = c1;
        }
    }
}

// ---------------------------------------------------------------------------
extern "C" void kernel_launch(void* const* d_in, const int* in_sizes, int n_in,
                              void* d_out, int out_size) {
    const float* node_attr   = (const float*)d_in[0];
    const float* edge_attr   = (const float*)d_in[1];
    const float* global_attr = (const float*)d_in[2];
    const float* W1          = (const float*)d_in[3];
    const float* b1          = (const float*)d_in[4];
    const float* W2          = (const float*)d_in[5];
    const float* b2          = (const float*)d_in[6];
    const int*   recv        = (const int*)d_in[7];
    const int*   ng          = (const int*)d_in[8];
    float* out = (float*)d_out;

    // 1) zero scratch + precompute G
    zero_kernel<<<1184, 256>>>(global_attr, W1, b1);

    // 2) edge scatter: 16M threads (16 per edge)
    {
        long long total = (long long)N_EDGES * 16;
        int threads = 256;
        int blocks = (int)((total + threads - 1) / threads);
        scatter_kernel<<<blocks, threads>>>(edge_attr, recv);
    }

    // 3) fused mean + MLP, 64 nodes per block
    mlp_kernel<<<(N_NODES + 63) / 64, 256>>>(node_attr, W1, W2, b2, ng, out);
}

// round 3
// speedup vs baseline: 1.4566x; 1.0043x over previous
#include <cuda_runtime.h>
#include <cstdint>

#define N_NODES 100000
#define N_EDGES 1000000
#define D 64
#define LATENT 32
#define OUT_DIM 64
#define XS_STRIDE 66

// Scratch (static device globals — BSS-zeroed at load; each mlp invocation
// re-zeros the portions it consumed, so state is invariant across calls)
__device__ float g_sums[(size_t)N_NODES * D];   // 25.6 MB
__device__ float g_cnt[N_NODES];
__device__ float g_G[64 * LATENT];              // global_attr @ W1[128:192] + b1

// ---------------------------------------------------------------------------
// f32x2 packed helpers (Blackwell FFMA2 — only reachable via PTX)
// ---------------------------------------------------------------------------
__device__ __forceinline__ uint64_t pack2(float a, float b) {
    uint64_t r; asm("mov.b64 %0, {%1, %2};" : "=l"(r) : "f"(a), "f"(b)); return r;
}
__device__ __forceinline__ void unpack2(uint64_t v, float& a, float& b) {
    asm("mov.b64 {%0, %1}, %2;" : "=f"(a), "=f"(b) : "l"(v));
}
__device__ __forceinline__ void ffma2(uint64_t& acc, uint64_t x, uint64_t w) {
    asm("fma.rn.f32x2 %0, %1, %2, %0;" : "+l"(acc) : "l"(x), "l"(w));
}

// ---------------------------------------------------------------------------
// Kernel 1: edge scatter (REDG.v4) + G precompute in block 0 (smem-staged so
// the latency chain of round 2 is gone; hidden under the other blocks).
// 16 threads per edge, each one float4 chunk.
// ---------------------------------------------------------------------------
__global__ __launch_bounds__(256)
void scatter_kernel(const float* __restrict__ edge_attr,
                    const int* __restrict__ recv,
                    const float* __restrict__ global_attr,
                    const float* __restrict__ W1,
                    const float* __restrict__ b1) {
    __shared__ float sg[64 * D];       // 16 KB global_attr
    __shared__ float sw[D * LATENT];   // 8 KB  W1 rows 128..191
    __shared__ float sb[LATENT];

    if (blockIdx.x == 0) {
        const int tid = threadIdx.x;
        for (int i = tid; i < (64 * D) / 4; i += 256)
            reinterpret_cast<float4*>(sg)[i] =
                reinterpret_cast<const float4*>(global_attr)[i];
        for (int i = tid; i < (D * LATENT) / 4; i += 256)
            reinterpret_cast<float4*>(sw)[i] =
                reinterpret_cast<const float4*>(W1 + 2 * D * LATENT)[i];
        if (tid < LATENT) sb[tid] = b1[tid];
        __syncthreads();

        const int j = tid & 31;
        const int r0 = (tid >> 5) * 8;
        float acc[8];
        #pragma unroll
        for (int i = 0; i < 8; i++) acc[i] = sb[j];
        #pragma unroll 8
        for (int k = 0; k < D; k++) {
            float w = sw[k * LATENT + j];
            #pragma unroll
            for (int i = 0; i < 8; i++)
                acc[i] = fmaf(sg[(r0 + i) * D + k], w, acc[i]);
        }
        #pragma unroll
        for (int i = 0; i < 8; i++) g_G[(r0 + i) * LATENT + j] = acc[i];
    }

    // ---- edge scatter ----
    long long gid = (long long)blockIdx.x * blockDim.x + threadIdx.x;
    int e = (int)(gid >> 4);
    int c = (int)(gid & 15);
    if (e >= N_EDGES) return;

    int r = __ldg(&recv[e]);
    float4 v = reinterpret_cast<const float4*>(edge_attr)[(size_t)e * 16 + c];
    float4* dst = reinterpret_cast<float4*>(g_sums) + (size_t)r * 16 + c;
    asm volatile("red.global.add.v4.f32 [%0], {%1, %2, %3, %4};"
                 :: "l"(dst), "f"(v.x), "f"(v.y), "f"(v.z), "f"(v.w)
                 : "memory");
    if (c == 0) atomicAdd(&g_cnt[r], 1.0f);
}

// ---------------------------------------------------------------------------
// Kernel 2: register-tiled fused mean + MLP with packed f32x2 FMA.
// Block = 64-node tile; lane = latent col; warp owns 8 nodes (4 f32x2 pairs).
// After consuming g_sums/g_cnt for its tile, the block re-zeros them so the
// next invocation starts clean (replaces the standalone zero kernel).
// ---------------------------------------------------------------------------
__global__ __launch_bounds__(256)
void mlp_kernel(const float* __restrict__ node_attr,
                const float* __restrict__ W1,
                const float* __restrict__ W2,
                const float* __restrict__ b2,
                const int* __restrict__ ng,
                float* __restrict__ out) {
    __shared__ float sW1[2 * D * LATENT];          // 16 KB: rows 0..127 of W1
    __shared__ float sW2[LATENT * OUT_DIM];        // 8 KB
    __shared__ float sb2[OUT_DIM];
    __shared__ __align__(16) float xs[D * XS_STRIDE];  // 16.9 KB, reused for h

    const int tid = threadIdx.x;
    const int tile = blockIdx.x * 64;

    for (int i = tid; i < 2 * D * LATENT; i += 256) sW1[i] = W1[i];
    for (int i = tid; i < LATENT * OUT_DIM; i += 256) sW2[i] = W2[i];
    if (tid < OUT_DIM) sb2[tid] = b2[tid];

    const int lane = tid & 31;
    const int p = tid >> 5;           // warp id = node group
    const int nbase = tile + p * 8;

    // init accumulators from precomputed global projection G
    uint64_t h2[4];
    #pragma unroll
    for (int q = 0; q < 4; q++) {
        int n0 = nbase + 2 * q, n1 = n0 + 1;
        int g0 = (n0 < N_NODES) ? __ldg(&ng[n0]) : 0;
        int g1 = (n1 < N_NODES) ? __ldg(&ng[n1]) : 0;
        h2[q] = pack2(g_G[g0 * LATENT + lane], g_G[g1 * LATENT + lane]);
    }

    const int kq = tid & 15;          // float4 slot: k = kq*4 .. kq*4+3
    const int srow = tid >> 4;        // node sub-slot 0..15

    // ---- pass 1: stage node_attr (k-major), accumulate k = 0..63 ----
    #pragma unroll
    for (int it = 0; it < 4; it++) {
        int nn = it * 16 + srow;
        int n = tile + nn;
        float4 v = make_float4(0.f, 0.f, 0.f, 0.f);
        if (n < N_NODES)
            v = reinterpret_cast<const float4*>(node_attr)[(size_t)n * 16 + kq];
        int k0 = kq * 4;
        xs[(k0 + 0) * XS_STRIDE + nn] = v.x;
        xs[(k0 + 1) * XS_STRIDE + nn] = v.y;
        xs[(k0 + 2) * XS_STRIDE + nn] = v.z;
        xs[(k0 + 3) * XS_STRIDE + nn] = v.w;
    }
    __syncthreads();

    #pragma unroll 4
    for (int k = 0; k < D; k++) {
        float w = sW1[k * LATENT + lane];
        uint64_t w2 = pack2(w, w);
        const uint64_t* xr =
            reinterpret_cast<const uint64_t*>(&xs[k * XS_STRIDE + p * 8]);
        #pragma unroll
        for (int q = 0; q < 4; q++) ffma2(h2[q], xr[q], w2);
    }
    __syncthreads();

    // ---- pass 2: stage mean aggregated edges, accumulate k = 64..127 ----
    #pragma unroll
    for (int it = 0; it < 4; it++) {
        int nn = it * 16 + srow;
        int n = tile + nn;
        float4 v = make_float4(0.f, 0.f, 0.f, 0.f);
        if (n < N_NODES) {
            v = reinterpret_cast<const float4*>(g_sums)[(size_t)n * 16 + kq];
            float inv = 1.0f / fmaxf(g_cnt[n], 1.0f);
            v.x *= inv; v.y *= inv; v.z *= inv; v.w *= inv;
        }
        int k0 = kq * 4;
        xs[(k0 + 0) * XS_STRIDE + nn] = v.x;
        xs[(k0 + 1) * XS_STRIDE + nn] = v.y;
        xs[(k0 + 2) * XS_STRIDE + nn] = v.z;
        xs[(k0 + 3) * XS_STRIDE + nn] = v.w;
    }
    __syncthreads();   // all reads of this tile's g_sums/g_cnt are done

    // ---- re-zero this tile's scratch for the next invocation ----
    {
        float4 z = make_float4(0.f, 0.f, 0.f, 0.f);
        #pragma unroll
        for (int it = 0; it < 4; it++) {
            int nn = it * 16 + srow;
            int n = tile + nn;
            if (n < N_NODES)
                reinterpret_cast<float4*>(g_sums)[(size_t)n * 16 + kq] = z;
        }
        if (tid < 64 && tile + tid < N_NODES) g_cnt[tile + tid] = 0.f;
    }

    #pragma unroll 4
    for (int k = 0; k < D; k++) {
        float w = sW1[(D + k) * LATENT + lane];
        uint64_t w2 = pack2(w, w);
        const uint64_t* xr =
            reinterpret_cast<const uint64_t*>(&xs[k * XS_STRIDE + p * 8]);
        #pragma unroll
        for (int q = 0; q < 4; q++) ffma2(h2[q], xr[q], w2);
    }
    __syncthreads();

    // ---- relu, park h in xs (j-major) ----
    #pragma unroll
    for (int q = 0; q < 4; q++) {
        float a, b;
        unpack2(h2[q], a, b);
        a = fmaxf(a, 0.f);
        b = fmaxf(b, 0.f);
        *reinterpret_cast<uint64_t*>(&xs[lane * XS_STRIDE + p * 8 + 2 * q]) =
            pack2(a, b);
    }
    __syncthreads();

    // ---- layer 2 ----
    uint64_t o2[4][2];
    #pragma unroll
    for (int q = 0; q < 4; q++) {
        o2[q][0] = pack2(sb2[lane], sb2[lane]);
        o2[q][1] = pack2(sb2[lane + 32], sb2[lane + 32]);
    }
    #pragma unroll 4
    for (int j = 0; j < LATENT; j++) {
        float wa = sW2[j * OUT_DIM + lane];
        float wb = sW2[j * OUT_DIM + lane + 32];
        uint64_t w0 = pack2(wa, wa);
        uint64_t w1 = pack2(wb, wb);
        const uint64_t* hr =
            reinterpret_cast<const uint64_t*>(&xs[j * XS_STRIDE + p * 8]);
        #pragma unroll
        for (int q = 0; q < 4; q++) {
            uint64_t x = hr[q];
            ffma2(o2[q][0], x, w0);
            ffma2(o2[q][1], x, w1);
        }
    }

    // ---- store ----
    #pragma unroll
    for (int q = 0; q < 4; q++) {
        int n0 = nbase + 2 * q;
        float a0, c0, a1, c1;
        unpack2(o2[q][0], a0, c0);  // a0 -> node n0, c0 -> node n0+1 (col lane)
        unpack2(o2[q][1], a1, c1);  // cols lane+32
        if (n0 < N_NODES) {
            out[(size_t)n0 * OUT_DIM + lane] = a0;
            out[(size_t)n0 * OUT_DIM + lane + 32] = a1;
        }
        if (n0 + 1 < N_NODES) {
            out[(size_t)(n0 + 1) * OUT_DIM + lane] = c0;
            out[(size_t)(n0 + 1) * OUT_DIM + lane + 32] = c1;
        }
    }
}

// ---------------------------------------------------------------------------
extern "C" void kernel_launch(void* const* d_in, const int* in_sizes, int n_in,
                              void* d_out, int out_size) {
    const float* node_attr   = (const float*)d_in[0];
    const float* edge_attr   = (const float*)d_in[1];
    const float* global_attr = (const float*)d_in[2];
    const float* W1          = (const float*)d_in[3];
    const float* b1          = (const float*)d_in[4];
    const float* W2          = (const float*)d_in[5];
    const float* b2          = (const float*)d_in[6];
    const int*   recv        = (const int*)d_in[7];
    const int*   ng          = (const int*)d_in[8];
    float* out = (float*)d_out;

    // 1) edge scatter (16 threads/edge) + G precompute in block 0
    {
        long long total = (long long)N_EDGES * 16;
        int threads = 256;
        int blocks = (int)((total + threads - 1) / threads);
        scatter_kernel<<<blocks, threads>>>(edge_attr, recv, global_attr, W1, b1);
    }

    // 2) fused mean + MLP (+ scratch re-zero), 64 nodes per block
    mlp_kernel<<<(N_NODES + 63) / 64, 256>>>(node_attr, W1, W2, b2, ng, out);
}

// round 4
// speedup vs baseline: 1.4657x; 1.0062x over previous
#include <cuda_runtime.h>
#include <cstdint>

#define N_NODES 100000
#define N_EDGES 1000000
#define D 64
#define LATENT 32
#define OUT_DIM 64
#define NB_NODE 1563              // node-projection blocks (64 nodes each)
#define NB_EDGE 62500             // 1M edges * 16 threads / 256
#define XS2_STRIDE 66             // float2 units; 528B rows -> 16B aligned

// Scratch (static device globals — BSS zeroed at load; mlp re-zeros consumed
// portions each call, so state is invariant across graph replays)
__device__ float g_sums[(size_t)N_NODES * D];       // 25.6 MB
__device__ float g_cnt[N_NODES];
__device__ float g_hpre[(size_t)N_NODES * LATENT];  // node_attr @ W1[0:64]
__device__ float g_G[64 * LATENT];                  // global @ W1[128:192] + b1

// ---------------------------------------------------------------------------
// f32x2 packed helpers (Blackwell FFMA2 — only reachable via PTX)
// ---------------------------------------------------------------------------
__device__ __forceinline__ uint64_t pack2(float a, float b) {
    uint64_t r; asm("mov.b64 %0, {%1, %2};" : "=l"(r) : "f"(a), "f"(b)); return r;
}
__device__ __forceinline__ void unpack2(uint64_t v, float& a, float& b) {
    asm("mov.b64 {%0, %1}, %2;" : "=f"(a), "=f"(b) : "l"(v));
}
__device__ __forceinline__ void ffma2(uint64_t& acc, uint64_t x, uint64_t w) {
    asm("fma.rn.f32x2 %0, %1, %2, %0;" : "+l"(acc) : "l"(x), "l"(w));
}

// ---------------------------------------------------------------------------
// Kernel A: [node-proj blocks | G block | edge-scatter blocks]
// ---------------------------------------------------------------------------
__global__ __launch_bounds__(256)
void scatter_kernel(const float* __restrict__ edge_attr,
                    const int* __restrict__ recv,
                    const float* __restrict__ node_attr,
                    const float* __restrict__ global_attr,
                    const float* __restrict__ W1,
                    const float* __restrict__ b1) {
    __shared__ __align__(16) char smem_raw[8192 + 16896 + 256];
    const int tid = threadIdx.x;

    if (blockIdx.x < NB_NODE) {
        // ---- node projection: hpre[n][j] = node_attr[n][0:64] . W1[0:64][j]
        float2* sW  = reinterpret_cast<float2*>(smem_raw);            // 8 KB
        float2* xs2 = reinterpret_cast<float2*>(smem_raw + 8192);     // 16.9 KB
        const int tile = blockIdx.x * 64;

        // stage W1 rows 0..63 interleaved: sW[k2*32+j] = (W1[2k2][j], W1[2k2+1][j])
        for (int idx = tid; idx < 1024; idx += 256) {
            int k2 = idx >> 5, j = idx & 31;
            sW[idx] = make_float2(W1[(2 * k2) * LATENT + j],
                                  (float)W1[(2 * k2 + 1) * LATENT + j]);
        }
        // stage node_attr interleaved-k
        const int kq = tid & 15, srow = tid >> 4;
        #pragma unroll
        for (int it = 0; it < 4; it++) {
            int nn = it * 16 + srow, n = tile + nn;
            float4 v = make_float4(0.f, 0.f, 0.f, 0.f);
            if (n < N_NODES)
                v = reinterpret_cast<const float4*>(node_attr)[(size_t)n * 16 + kq];
            xs2[(2 * kq + 0) * XS2_STRIDE + nn] = make_float2(v.x, v.y);
            xs2[(2 * kq + 1) * XS2_STRIDE + nn] = make_float2(v.z, v.w);
        }
        __syncthreads();

        const int lane = tid & 31, p = tid >> 5;
        uint64_t a2[8];
        #pragma unroll
        for (int i = 0; i < 8; i++) a2[i] = pack2(0.f, 0.f);

        #pragma unroll 4
        for (int k2 = 0; k2 < 32; k2++) {
            uint64_t w2 = *reinterpret_cast<const uint64_t*>(&sW[k2 * 32 + lane]);
            const uint64_t* xr =
                reinterpret_cast<const uint64_t*>(&xs2[k2 * XS2_STRIDE + p * 8]);
            #pragma unroll
            for (int i = 0; i < 8; i++) ffma2(a2[i], xr[i], w2);
        }
        #pragma unroll
        for (int i = 0; i < 8; i++) {
            float lo, hi; unpack2(a2[i], lo, hi);
            int n = tile + p * 8 + i;
            if (n < N_NODES) g_hpre[(size_t)n * LATENT + lane] = lo + hi;
        }
        return;
    }

    if (blockIdx.x == NB_NODE) {
        // ---- G[b][j] = b1[j] + global[b] . W1[128:192][j]  (smem-staged)
        float* sg = reinterpret_cast<float*>(smem_raw);           // 16 KB
        float* sw = reinterpret_cast<float*>(smem_raw + 16384);   // 8 KB
        float* sb = reinterpret_cast<float*>(smem_raw + 24576);
        for (int i = tid; i < (64 * D) / 4; i += 256)
            reinterpret_cast<float4*>(sg)[i] =
                reinterpret_cast<const float4*>(global_attr)[i];
        for (int i = tid; i < (D * LATENT) / 4; i += 256)
            reinterpret_cast<float4*>(sw)[i] =
                reinterpret_cast<const float4*>(W1 + 2 * D * LATENT)[i];
        if (tid < LATENT) sb[tid] = b1[tid];
        __syncthreads();

        const int j = tid & 31, r0 = (tid >> 5) * 8;
        float acc[8];
        #pragma unroll
        for (int i = 0; i < 8; i++) acc[i] = sb[j];
        #pragma unroll 8
        for (int k = 0; k < D; k++) {
            float w = sw[k * LATENT + j];
            #pragma unroll
            for (int i = 0; i < 8; i++)
                acc[i] = fmaf(sg[(r0 + i) * D + k], w, acc[i]);
        }
        #pragma unroll
        for (int i = 0; i < 8; i++) g_G[(r0 + i) * LATENT + j] = acc[i];
        return;
    }

    // ---- edge scatter: 16 threads/edge, vectorized L2 reduction
    long long gid = (long long)(blockIdx.x - (NB_NODE + 1)) * 256 + tid;
    int e = (int)(gid >> 4);
    int c = (int)(gid & 15);
    if (e >= N_EDGES) return;

    int r = __ldg(&recv[e]);
    float4 v = reinterpret_cast<const float4*>(edge_attr)[(size_t)e * 16 + c];
    float4* dst = reinterpret_cast<float4*>(g_sums) + (size_t)r * 16 + c;
    asm volatile("red.global.add.v4.f32 [%0], {%1, %2, %3, %4};"
                 :: "l"(dst), "f"(v.x), "f"(v.y), "f"(v.z), "f"(v.w)
                 : "memory");
    if (c == 0) atomicAdd(&g_cnt[r], 1.0f);
}

// ---------------------------------------------------------------------------
// Kernel B: fused mean + (edge half of layer 1) + relu + layer 2.
// Block = 64-node tile; lane = latent col; warp owns 8 nodes.
// Re-zeros its tile of g_sums/g_cnt for the next replay.
// ---------------------------------------------------------------------------
__global__ __launch_bounds__(256)
void mlp_kernel(const float* __restrict__ W1,
                const float* __restrict__ W2,
                const float* __restrict__ b2,
                const int* __restrict__ ng,
                float* __restrict__ out) {
    __shared__ __align__(16) float2 sW1b[1024];            // 8 KB, rows 64..127
    __shared__ float sW2[LATENT * OUT_DIM];                // 8 KB
    __shared__ float sb2[OUT_DIM];
    __shared__ __align__(16) float2 xs2[32 * XS2_STRIDE];  // 16.9 KB (reused for h)

    const int tid = threadIdx.x;
    const int tile = blockIdx.x * 64;
    const int lane = tid & 31, p = tid >> 5;
    const int nbase = tile + p * 8;

    for (int idx = tid; idx < 1024; idx += 256) {
        int k2 = idx >> 5, j = idx & 31;
        sW1b[idx] = make_float2(W1[(D + 2 * k2) * LATENT + j],
                                (float)W1[(D + 2 * k2 + 1) * LATENT + j]);
    }
    for (int i = tid; i < LATENT * OUT_DIM; i += 256) sW2[i] = W2[i];
    if (tid < OUT_DIM) sb2[tid] = b2[tid];

    // init accumulators: lo = hpre + G, hi = 0
    uint64_t a2[8];
    #pragma unroll
    for (int i = 0; i < 8; i++) {
        int n = nbase + i;
        float init = 0.f;
        if (n < N_NODES) {
            int g = __ldg(&ng[n]);
            init = g_hpre[(size_t)n * LATENT + lane] + g_G[g * LATENT + lane];
        }
        a2[i] = pack2(init, 0.f);
    }

    // stage mean aggregated edges, interleaved-k float2
    const int kq = tid & 15, srow = tid >> 4;
    #pragma unroll
    for (int it = 0; it < 4; it++) {
        int nn = it * 16 + srow, n = tile + nn;
        float4 v = make_float4(0.f, 0.f, 0.f, 0.f);
        if (n < N_NODES) {
            v = reinterpret_cast<const float4*>(g_sums)[(size_t)n * 16 + kq];
            float inv = 1.0f / fmaxf(g_cnt[n], 1.0f);
            v.x *= inv; v.y *= inv; v.z *= inv; v.w *= inv;
        }
        xs2[(2 * kq + 0) * XS2_STRIDE + nn] = make_float2(v.x, v.y);
        xs2[(2 * kq + 1) * XS2_STRIDE + nn] = make_float2(v.z, v.w);
    }
    __syncthreads();

    // re-zero this tile's scratch (all reads of it are done)
    {
        float4 z = make_float4(0.f, 0.f, 0.f, 0.f);
        #pragma unroll
        for (int it = 0; it < 4; it++) {
            int n = tile + it * 16 + srow;
            if (n < N_NODES)
                reinterpret_cast<float4*>(g_sums)[(size_t)n * 16 + kq] = z;
        }
        if (tid < 64 && tile + tid < N_NODES) g_cnt[tile + tid] = 0.f;
    }

    // edge half of layer 1: FFMA2 over k-pairs
    #pragma unroll 4
    for (int k2 = 0; k2 < 32; k2++) {
        uint64_t w2 = *reinterpret_cast<const uint64_t*>(&sW1b[k2 * 32 + lane]);
        const uint64_t* xr =
            reinterpret_cast<const uint64_t*>(&xs2[k2 * XS2_STRIDE + p * 8]);
        #pragma unroll
        for (int i = 0; i < 8; i++) ffma2(a2[i], xr[i], w2);
    }
    __syncthreads();   // xs2 reads done; safe to overwrite with h

    // relu(lo+hi), park h j-major as node pairs
    float* hs = reinterpret_cast<float*>(xs2);   // rows: j * XS2_STRIDE (floats ok)
    float h[8];
    #pragma unroll
    for (int i = 0; i < 8; i++) {
        float lo, hi; unpack2(a2[i], lo, hi);
        h[i] = fmaxf(lo + hi, 0.f);
    }
    #pragma unroll
    for (int q = 0; q < 4; q++)
        *reinterpret_cast<uint64_t*>(&hs[lane * (2 * XS2_STRIDE) + p * 8 + 2 * q]) =
            pack2(h[2 * q], h[2 * q + 1]);
    __syncthreads();

    // layer 2
    uint64_t o2[4][2];
    #pragma unroll
    for (int q = 0; q < 4; q++) {
        o2[q][0] = pack2(sb2[lane], sb2[lane]);
        o2[q][1] = pack2(sb2[lane + 32], sb2[lane + 32]);
    }
    #pragma unroll 4
    for (int j = 0; j < LATENT; j++) {
        float wa = sW2[j * OUT_DIM + lane];
        float wb = sW2[j * OUT_DIM + lane + 32];
        uint64_t w0 = pack2(wa, wa);
        uint64_t w1 = pack2(wb, wb);
        const uint64_t* hr =
            reinterpret_cast<const uint64_t*>(&hs[j * (2 * XS2_STRIDE) + p * 8]);
        #pragma unroll
        for (int q = 0; q < 4; q++) {
            uint64_t x = hr[q];
            ffma2(o2[q][0], x, w0);
            ffma2(o2[q][1], x, w1);
        }
    }

    // store
    #pragma unroll
    for (int q = 0; q < 4; q++) {
        int n0 = nbase + 2 * q;
        float a0, c0, a1, c1;
        unpack2(o2[q][0], a0, c0);
        unpack2(o2[q][1], a1, c1);
        if (n0 < N_NODES) {
            out[(size_t)n0 * OUT_DIM + lane]      = a0;
            out[(size_t)n0 * OUT_DIM + lane + 32] = a1;
        }
        if (n0 + 1 < N_NODES) {
            out[(size_t)(n0 + 1) * OUT_DIM + lane]      = c0;
            out[(size_t)(n0 + 1) * OUT_DIM + lane + 32] = c1;
        }
    }
}

// ---------------------------------------------------------------------------
extern "C" void kernel_launch(void* const* d_in, const int* in_sizes, int n_in,
                              void* d_out, int out_size) {
    const float* node_attr   = (const float*)d_in[0];
    const float* edge_attr   = (const float*)d_in[1];
    const float* global_attr = (const float*)d_in[2];
    const float* W1          = (const float*)d_in[3];
    const float* b1          = (const float*)d_in[4];
    const float* W2          = (const float*)d_in[5];
    const float* b2          = (const float*)d_in[6];
    const int*   recv        = (const int*)d_in[7];
    const int*   ng          = (const int*)d_in[8];
    float* out = (float*)d_out;

    // A) node-proj + G + edge scatter in one grid
    scatter_kernel<<<NB_NODE + 1 + NB_EDGE, 256>>>(edge_attr, recv, node_attr,
                                                   global_attr, W1, b1);

    // B) fused mean + MLP (+ scratch re-zero), 64 nodes per block
    mlp_kernel<<<(N_NODES + 63) / 64, 256>>>(W1, W2, b2, ng, out);
}